// round 8
// baseline (speedup 1.0000x reference)
#include <cuda_runtime.h>

// GIoU loss mean over N=4,000,000 box pairs. Single fused kernel.
// 4-wave oversubscribed grid (4736 CTAs): HW work-stealing lets near-die
// (fast) SMs take more CTAs, shrinking the straggler tail that capped the
// single-wave version at ~67% DRAM. Deterministic: per-CTA partial slots,
// fixed-order final reduce.

#define NBLOCKS 4736   // 4 waves of 148 SMs x 8 CTAs
#define NTHREADS 256

__device__ float g_partials[NBLOCKS];
__device__ unsigned int g_count;   // zero at load; last block resets -> replay-safe

__device__ __forceinline__ float giou_term(float4 p, float4 t) {
    float area_p = (p.z - p.x) * (p.w - p.y);
    float area_t = (t.z - t.x) * (t.w - t.y);

    float iw = fmaxf(fminf(p.z, t.z) - fmaxf(p.x, t.x), 0.0f);
    float ih = fmaxf(fminf(p.w, t.w) - fmaxf(p.y, t.y), 0.0f);
    float inter = iw * ih;
    float uni   = area_p + area_t - inter;

    float cw = fmaxf(p.z, t.z) - fminf(p.x, t.x);
    float ch = fmaxf(p.w, t.w) - fminf(p.y, t.y);
    float area_c = cw * ch;

    // iou + union/area_c  ("2 -" folded out of the loop)
    float num = fmaf(uni, uni, inter * area_c);
    float den = uni * area_c;
    return __fdividef(num, den);
}

__global__ __launch_bounds__(NTHREADS, 6)
void giou_fused_kernel(const float4* __restrict__ pred,
                       const float4* __restrict__ tgt,
                       float* __restrict__ out,
                       int n, float inv_n) {
    const int stride = gridDim.x * blockDim.x;
    int i = blockIdx.x * blockDim.x + threadIdx.x;

    float acc = 0.0f;

    // ~3.3 iterations/thread; unroll x2 keeps 4 LDG.128 in flight.
    for (; i + stride < n; i += 2 * stride) {
        float4 p0 = __ldcs(&pred[i]);
        float4 t0 = __ldcs(&tgt[i]);
        float4 p1 = __ldcs(&pred[i + stride]);
        float4 t1 = __ldcs(&tgt[i + stride]);
        acc += giou_term(p0, t0);
        acc += giou_term(p1, t1);
    }
    if (i < n)
        acc += giou_term(__ldcs(&pred[i]), __ldcs(&tgt[i]));

    // Intra-block reduction (fixed order -> deterministic)
    #pragma unroll
    for (int o = 16; o > 0; o >>= 1)
        acc += __shfl_xor_sync(0xffffffffu, acc, o);

    __shared__ float s[NTHREADS / 32];
    if ((threadIdx.x & 31) == 0) s[threadIdx.x >> 5] = acc;
    __syncthreads();

    __shared__ bool is_last;
    if (threadIdx.x == 0) {
        float v = 0.0f;
        #pragma unroll
        for (int w = 0; w < NTHREADS / 32; w++) v += s[w];
        g_partials[blockIdx.x] = v;
        __threadfence();
        unsigned int prev = atomicAdd(&g_count, 1u);
        is_last = (prev == (unsigned int)(gridDim.x - 1));
    }
    __syncthreads();

    if (!is_last) return;

    // Last block: reduce all 4736 partials (L2-hot), deterministic order.
    float v = 0.0f;
    for (int b = threadIdx.x; b < NBLOCKS; b += NTHREADS)
        v += g_partials[b];

    #pragma unroll
    for (int o = 16; o > 0; o >>= 1)
        v += __shfl_xor_sync(0xffffffffu, v, o);

    __shared__ float s2[NTHREADS / 32];
    if ((threadIdx.x & 31) == 0) s2[threadIdx.x >> 5] = v;
    __syncthreads();

    if (threadIdx.x == 0) {
        float r = 0.0f;
        #pragma unroll
        for (int w = 0; w < NTHREADS / 32; w++) r += s2[w];
        *out = 2.0f - r * inv_n;   // mean(1 - giou)
        g_count = 0;               // reset for next replay
    }
}

extern "C" void kernel_launch(void* const* d_in, const int* in_sizes, int n_in,
                              void* d_out, int out_size) {
    const float4* pred = (const float4*)d_in[0];
    const float4* tgt  = (const float4*)d_in[1];
    float* out = (float*)d_out;

    const int n = in_sizes[0] / 4;   // floats -> boxes

    giou_fused_kernel<<<NBLOCKS, NTHREADS>>>(pred, tgt, out, n, 1.0f / (float)n);
}

// round 9
// speedup vs baseline: 1.1484x; 1.1484x over previous
#include <cuda_runtime.h>

// GIoU loss mean over N=4,000,000 box pairs.
// Persistent single-wave grid + dynamic chunk ticketing: fast (near-die) SMs
// grab more 1024-box chunks, killing the static-partition straggler tail that
// capped DRAM at ~67%. Ticket prefetched one chunk ahead so ATOMG latency
// hides behind streaming. Last-block-done fused reduction; counters reset by
// the last block -> graph-replay safe.

#define NBLOCKS  1184   // one full wave: 148 SMs x 8 CTAs
#define NTHREADS 256
#define CHUNK    1024   // boxes per chunk: 32 KB of reads, 4 pairs/thread

__device__ float g_partials[NBLOCKS];
__device__ unsigned int g_count;    // zero at load; last block resets
__device__ unsigned int g_ticket;   // zero at load; last block resets

__device__ __forceinline__ float giou_term(float4 p, float4 t) {
    float area_p = (p.z - p.x) * (p.w - p.y);
    float area_t = (t.z - t.x) * (t.w - t.y);

    float iw = fmaxf(fminf(p.z, t.z) - fmaxf(p.x, t.x), 0.0f);
    float ih = fmaxf(fminf(p.w, t.w) - fmaxf(p.y, t.y), 0.0f);
    float inter = iw * ih;
    float uni   = area_p + area_t - inter;

    float cw = fmaxf(p.z, t.z) - fminf(p.x, t.x);
    float ch = fmaxf(p.w, t.w) - fminf(p.y, t.y);
    float area_c = cw * ch;

    // iou + union/area_c  ("2 -" folded out of the loop)
    float num = fmaf(uni, uni, inter * area_c);
    float den = uni * area_c;
    return __fdividef(num, den);
}

__global__ __launch_bounds__(NTHREADS, 6)
void giou_fused_kernel(const float4* __restrict__ pred,
                       const float4* __restrict__ tgt,
                       float* __restrict__ out,
                       int n, float inv_n) {
    const int n_chunks = (n + CHUNK - 1) / CHUNK;

    __shared__ int s_next[2];
    int parity = 0;

    if (threadIdx.x == 0) s_next[0] = (int)atomicAdd(&g_ticket, 1u);
    __syncthreads();
    int cur = s_next[0];

    float acc = 0.0f;

    while (cur < n_chunks) {
        // Prefetch next ticket: ATOMG latency hides behind this chunk's loads.
        if (threadIdx.x == 0) s_next[parity ^ 1] = (int)atomicAdd(&g_ticket, 1u);

        const int base = cur * CHUNK + threadIdx.x;

        if (base + 3 * NTHREADS < n) {          // full chunk, no guards
            // Pair 1+2: MLP 4 (matches proven R6 shape)
            float4 p0 = __ldcs(&pred[base]);
            float4 t0 = __ldcs(&tgt [base]);
            float4 p1 = __ldcs(&pred[base + NTHREADS]);
            float4 t1 = __ldcs(&tgt [base + NTHREADS]);
            acc += giou_term(p0, t0);
            acc += giou_term(p1, t1);
            // Pair 3+4
            float4 p2 = __ldcs(&pred[base + 2 * NTHREADS]);
            float4 t2 = __ldcs(&tgt [base + 2 * NTHREADS]);
            float4 p3 = __ldcs(&pred[base + 3 * NTHREADS]);
            float4 t3 = __ldcs(&tgt [base + 3 * NTHREADS]);
            acc += giou_term(p2, t2);
            acc += giou_term(p3, t3);
        } else {                                 // last partial chunk
            #pragma unroll
            for (int k = 0; k < 4; k++) {
                int idx = base + k * NTHREADS;
                if (idx < n)
                    acc += giou_term(__ldcs(&pred[idx]), __ldcs(&tgt[idx]));
            }
        }

        __syncthreads();          // next ticket visible; s_next slot reusable
        parity ^= 1;
        cur = s_next[parity];
    }

    // Intra-block reduction (fixed tree)
    #pragma unroll
    for (int o = 16; o > 0; o >>= 1)
        acc += __shfl_xor_sync(0xffffffffu, acc, o);

    __shared__ float s[NTHREADS / 32];
    if ((threadIdx.x & 31) == 0) s[threadIdx.x >> 5] = acc;
    __syncthreads();

    __shared__ bool is_last;
    if (threadIdx.x == 0) {
        float v = 0.0f;
        #pragma unroll
        for (int w = 0; w < NTHREADS / 32; w++) v += s[w];
        g_partials[blockIdx.x] = v;
        __threadfence();
        unsigned int prev = atomicAdd(&g_count, 1u);
        is_last = (prev == (unsigned int)(gridDim.x - 1));
    }
    __syncthreads();

    if (!is_last) return;

    // Last block: reduce all 1184 partials (L2-hot), fixed order.
    float v = 0.0f;
    for (int b = threadIdx.x; b < NBLOCKS; b += NTHREADS)
        v += g_partials[b];

    #pragma unroll
    for (int o = 16; o > 0; o >>= 1)
        v += __shfl_xor_sync(0xffffffffu, v, o);

    __shared__ float s2[NTHREADS / 32];
    if ((threadIdx.x & 31) == 0) s2[threadIdx.x >> 5] = v;
    __syncthreads();

    if (threadIdx.x == 0) {
        float r = 0.0f;
        #pragma unroll
        for (int w = 0; w < NTHREADS / 32; w++) r += s2[w];
        *out = 2.0f - r * inv_n;   // mean(1 - giou)
        g_count  = 0;              // reset for next replay
        g_ticket = 0;
    }
}

extern "C" void kernel_launch(void* const* d_in, const int* in_sizes, int n_in,
                              void* d_out, int out_size) {
    const float4* pred = (const float4*)d_in[0];
    const float4* tgt  = (const float4*)d_in[1];
    float* out = (float*)d_out;

    const int n = in_sizes[0] / 4;   // floats -> boxes

    giou_fused_kernel<<<NBLOCKS, NTHREADS>>>(pred, tgt, out, n, 1.0f / (float)n);
}